// round 4
// baseline (speedup 1.0000x reference)
#include <cuda_runtime.h>

// Problem geometry (fixed by reference)
#define NCH    2560      // readout channels
#define NT     256       // ticks
#define NT2    128       // float2 per row
#define NCELLS 40000     // cells per face
#define CAP    320       // max entries per output channel (Poisson(~100) tail-safe)

// ---- static device scratch (no allocation allowed) ----
__device__ int     g_counts[NCH];
__device__ float   g_xr[NCH * NT];          // relu(x) staging, 2.6 MB
__device__ ushort4 g_entries[NCH * CAP];    // per-channel cell lists, 6.55 MB
__device__ float   g_wf[8];                 // folded weights: w00,w10,w20,w01,w11,w21,be0,be1

// Read logical element i from an index table that may be int32 or int64
// (little-endian: lo word first; all values nonnegative < 2^31).
__device__ __forceinline__ int idx_ld(const int* p, int i, bool is64) {
    return is64 ? p[2 * i] : p[i];
}

// Kernel 1a: zero counts + stage relu(x).
__global__ void prep_kernel(const float* __restrict__ x) {
    int i = blockIdx.x * blockDim.x + threadIdx.x;
    if (i < NCH) g_counts[i] = 0;
    if (i < NCH * NT / 4) {
        float4 v = ((const float4*)x)[i];
        v.x = fmaxf(v.x, 0.f); v.y = fmaxf(v.y, 0.f);
        v.z = fmaxf(v.z, 0.f); v.w = fmaxf(v.w, 0.f);
        ((float4*)g_xr)[i] = v;
    }
}

// Kernel 1b: fold W1(3x8)@W2(8x2) and beff = b1@W2 + b2 once (1 thread).
__global__ void fold_kernel(const float* __restrict__ W1, const float* __restrict__ b1,
                            const float* __restrict__ W2, const float* __restrict__ b2) {
    if (threadIdx.x != 0) return;
    float s0 = b2[0], s1 = b2[1];
    float a[6] = {0.f, 0.f, 0.f, 0.f, 0.f, 0.f};   // w00,w10,w20,w01,w11,w21
    #pragma unroll
    for (int h = 0; h < 8; ++h) {
        float v0 = W2[h * 2 + 0], v1 = W2[h * 2 + 1];
        s0 = fmaf(b1[h], v0, s0);
        s1 = fmaf(b1[h], v1, s1);
        #pragma unroll
        for (int r = 0; r < 3; ++r) {
            a[r]     = fmaf(W1[r * 8 + h], v0, a[r]);
            a[r + 3] = fmaf(W1[r * 8 + h], v1, a[r + 3]);
        }
    }
    #pragma unroll
    for (int r = 0; r < 6; ++r) g_wf[r] = a[r];
    g_wf[6] = s0; g_wf[7] = s1;
}

// Kernel 2: build per-output-channel entry lists.
// For each (face, cell): resolve the 3 plane channels via wc tables, append
// the (c0,c1,c2) triple to each of the 3 target channels' buckets.
__global__ void build_kernel(const int* __restrict__ gi0, const int* __restrict__ gi1,
                             const int* __restrict__ wc00, const int* __restrict__ wc01,
                             const int* __restrict__ wc02, const int* __restrict__ wc10,
                             const int* __restrict__ wc11, const int* __restrict__ wc12) {
    int gid = blockIdx.x * blockDim.x + threadIdx.x;
    if (gid >= 2 * NCELLS) return;
    // dtype sniff: int64 => those words are hi-halves (all 0). For int32 they
    // are distinct permutation channels (at most one can be 0).
    bool is64 = (wc00[1] == 0 && wc00[3] == 0 && wc00[5] == 0);
    int f = gid / NCELLS;
    int n = gid - f * NCELLS;
    const int* gi = f ? gi1 : gi0;
    const int* wa = f ? wc10 : wc00;
    const int* wb = f ? wc11 : wc01;
    const int* wd = f ? wc12 : wc02;

    int w0 = idx_ld(gi, n * 3 + 0, is64);
    int w1 = idx_ld(gi, n * 3 + 1, is64);
    int w2 = idx_ld(gi, n * 3 + 2, is64);
    int c0 = idx_ld(wa, w0 * 2 + 1, is64);
    int c1 = idx_ld(wb, w1 * 2 + 1, is64);
    int c2 = idx_ld(wd, w2 * 2 + 1, is64);

    ushort4 e = make_ushort4((unsigned short)c0, (unsigned short)c1,
                             (unsigned short)c2, 0);
    int s0 = atomicAdd(&g_counts[c0], 1);
    if (s0 < CAP) g_entries[c0 * CAP + s0] = e;
    int s1 = atomicAdd(&g_counts[c1], 1);
    if (s1 < CAP) g_entries[c1 * CAP + s1] = e;
    int s2 = atomicAdd(&g_counts[c2], 1);
    if (s2 < CAP) g_entries[c2 * CAP + s2] = e;
}

// Kernel 3: one block per output channel; 128 threads, 2 ticks each (float2).
// Gather-max over this channel's cell list using the folded 3x2 linear map.
__global__ __launch_bounds__(128) void main_kernel(float* __restrict__ out) {
    int c   = blockIdx.x;
    int tid = threadIdx.x;   // 0..127

    float w00 = g_wf[0], w10 = g_wf[1], w20 = g_wf[2];
    float w01 = g_wf[3], w11 = g_wf[4], w21 = g_wf[5];
    float be0 = g_wf[6], be1 = g_wf[7];

    __shared__ ushort4 sE[CAP];
    int cnt = min(g_counts[c], CAP);
    for (int i = tid; i < cnt; i += 128) sE[i] = g_entries[c * CAP + i];
    __syncthreads();

    const float2* xr2 = (const float2*)g_xr;
    float m0x = 0.f, m0y = 0.f, m1x = 0.f, m1y = 0.f;

    #pragma unroll 8
    for (int i = 0; i < cnt; ++i) {
        ushort4 e = sE[i];
        float2 a0 = xr2[(int)e.x * NT2 + tid];
        float2 a1 = xr2[(int)e.y * NT2 + tid];
        float2 a2 = xr2[(int)e.z * NT2 + tid];
        float y0x = fmaf(a0.x, w00, fmaf(a1.x, w10, fmaf(a2.x, w20, be0)));
        float y0y = fmaf(a0.y, w00, fmaf(a1.y, w10, fmaf(a2.y, w20, be0)));
        float y1x = fmaf(a0.x, w01, fmaf(a1.x, w11, fmaf(a2.x, w21, be1)));
        float y1y = fmaf(a0.y, w01, fmaf(a1.y, w11, fmaf(a2.y, w21, be1)));
        m0x = fmaxf(m0x, y0x); m0y = fmaxf(m0y, y0y);
        m1x = fmaxf(m1x, y1x); m1y = fmaxf(m1y, y1y);
    }

    // out layout: (1, 3, NCH, NT) fp32.  Plane 0 = relu(x); planes 1,2 = scatter-max.
    float2* o2 = (float2*)out;
    o2[c * NT2 + tid]                 = xr2[c * NT2 + tid];
    o2[NCH * NT2 + c * NT2 + tid]     = make_float2(m0x, m0y);
    o2[2 * NCH * NT2 + c * NT2 + tid] = make_float2(m1x, m1y);
}

extern "C" void kernel_launch(void* const* d_in, const int* in_sizes, int n_in,
                              void* d_out, int out_size) {
    const float* x  = (const float*)d_in[0];
    const float* W1 = (const float*)d_in[1];
    const float* b1 = (const float*)d_in[2];
    const float* W2 = (const float*)d_in[3];
    const float* b2 = (const float*)d_in[4];
    const int* gi0  = (const int*)d_in[5];
    const int* gi1  = (const int*)d_in[6];
    const int* wc00 = (const int*)d_in[7];
    const int* wc01 = (const int*)d_in[8];
    const int* wc02 = (const int*)d_in[9];
    const int* wc10 = (const int*)d_in[10];
    const int* wc11 = (const int*)d_in[11];
    const int* wc12 = (const int*)d_in[12];

    prep_kernel<<<(NCH * NT / 4 + 255) / 256, 256>>>(x);
    fold_kernel<<<1, 32>>>(W1, b1, W2, b2);
    build_kernel<<<(2 * NCELLS + 255) / 256, 256>>>(gi0, gi1, wc00, wc01, wc02,
                                                    wc10, wc11, wc12);
    main_kernel<<<NCH, 128>>>((float*)d_out);
}

// round 7
// speedup vs baseline: 1.5486x; 1.5486x over previous
#include <cuda_runtime.h>

// Problem geometry (fixed by reference)
#define NCH    2560      // readout channels
#define NT     256       // ticks
#define NT4    64        // float4 per row
#define NCELLS 40000     // cells per face
#define CAP    320       // max entries per output channel (Poisson(~100) tail-safe)

// ---- static device scratch (no allocation allowed) ----
__device__ int     g_counts[NCH];           // zero-init at load; main_kernel re-zeroes
__device__ float   g_xr[NCH * NT];          // relu(x) staging, 2.6 MB
__device__ ushort2 g_entries[NCH * CAP];    // per-channel partner pairs, 3.3 MB
__device__ float   g_wf[8];                 // folded: w00,w10,w20,w01,w11,w21,be0,be1

// Read logical element i from an index table that may be int32 or int64
// (little-endian: lo word first; all values nonnegative < 2^31).
__device__ __forceinline__ int idx_ld(const int* p, int i, bool is64) {
    return is64 ? p[2 * i] : p[i];
}

#define PREP_BLOCKS  640                    // 640*256 threads, one float4 each = NCH*NT/4
#define BUILD_BLOCKS 313                    // ceil(80000/256)

// Fused pre-kernel: relu-stage + out plane0 (blocks [0,PREP)), bucket build
// (blocks [PREP, PREP+BUILD)), weight fold (last block). The three roles are
// independent; g_counts is already zero (module init on run 1, main_kernel
// resets it at the end of every run).
__global__ void pre_kernel(const float* __restrict__ x, float* __restrict__ out,
                           const float* __restrict__ W1, const float* __restrict__ b1,
                           const float* __restrict__ W2, const float* __restrict__ b2,
                           const int* __restrict__ gi0, const int* __restrict__ gi1,
                           const int* __restrict__ wc00, const int* __restrict__ wc01,
                           const int* __restrict__ wc02, const int* __restrict__ wc10,
                           const int* __restrict__ wc11, const int* __restrict__ wc12) {
    int b = blockIdx.x, tid = threadIdx.x;
    if (b < PREP_BLOCKS) {
        int i = b * 256 + tid;                      // float4 index, < NCH*NT/4 = 163840
        float4 v = ((const float4*)x)[i];
        v.x = fmaxf(v.x, 0.f); v.y = fmaxf(v.y, 0.f);
        v.z = fmaxf(v.z, 0.f); v.w = fmaxf(v.w, 0.f);
        ((float4*)g_xr)[i] = v;
        ((float4*)out)[i]  = v;                     // output plane 0 = relu(x)
        return;
    }
    if (b < PREP_BLOCKS + BUILD_BLOCKS) {
        int gid = (b - PREP_BLOCKS) * 256 + tid;
        if (gid >= 2 * NCELLS) return;
        // dtype sniff: int64 => these words are hi-halves (all 0). For int32
        // they are three distinct permutation channels (at most one can be 0).
        bool is64 = (wc00[1] == 0 && wc00[3] == 0 && wc00[5] == 0);
        int f = gid / NCELLS;
        int n = gid - f * NCELLS;
        const int* gi = f ? gi1 : gi0;
        const int* wa = f ? wc10 : wc00;
        const int* wb = f ? wc11 : wc01;
        const int* wd = f ? wc12 : wc02;

        int w0 = idx_ld(gi, n * 3 + 0, is64);
        int w1 = idx_ld(gi, n * 3 + 1, is64);
        int w2 = idx_ld(gi, n * 3 + 2, is64);
        int c0 = idx_ld(wa, w0 * 2 + 1, is64);      // plane 0, in [0,800)
        int c1 = idx_ld(wb, w1 * 2 + 1, is64);      // plane 1, in [800,1600)
        int c2 = idx_ld(wd, w2 * 2 + 1, is64);      // plane 2, in [1600,2560)

        // Bucket c stores the OTHER two channels (slot implied by c's range).
        int s0 = atomicAdd(&g_counts[c0], 1);
        if (s0 < CAP) g_entries[c0 * CAP + s0] =
            make_ushort2((unsigned short)c1, (unsigned short)c2);
        int s1 = atomicAdd(&g_counts[c1], 1);
        if (s1 < CAP) g_entries[c1 * CAP + s1] =
            make_ushort2((unsigned short)c0, (unsigned short)c2);
        int s2 = atomicAdd(&g_counts[c2], 1);
        if (s2 < CAP) g_entries[c2 * CAP + s2] =
            make_ushort2((unsigned short)c0, (unsigned short)c1);
        return;
    }
    // fold block: W1(3x8)@W2(8x2), beff = b1@W2 + b2
    if (tid == 0) {
        float s0 = b2[0], s1 = b2[1];
        float a[6] = {0.f, 0.f, 0.f, 0.f, 0.f, 0.f};
        #pragma unroll
        for (int h = 0; h < 8; ++h) {
            float v0 = W2[h * 2 + 0], v1 = W2[h * 2 + 1];
            s0 = fmaf(b1[h], v0, s0);
            s1 = fmaf(b1[h], v1, s1);
            #pragma unroll
            for (int r = 0; r < 3; ++r) {
                a[r]     = fmaf(W1[r * 8 + h], v0, a[r]);
                a[r + 3] = fmaf(W1[r * 8 + h], v1, a[r + 3]);
            }
        }
        #pragma unroll
        for (int r = 0; r < 6; ++r) g_wf[r] = a[r];
        g_wf[6] = s0; g_wf[7] = s1;
    }
}

// Main: one block per output channel; 64 threads, 4 ticks each (float4).
// Self-row contribution is hoisted into a per-thread base; per entry we load
// only the 2 partner rows and do 16 FMA + 8 FMNMX across 4 ticks.
__global__ __launch_bounds__(64) void main_kernel(float* __restrict__ out) {
    int c   = blockIdx.x;
    int tid = threadIdx.x;   // 0..63

    int slot = (c >= 800) + (c >= 1600);            // plane of channel c
    float ws0 = g_wf[slot],              ws1 = g_wf[3 + slot];
    float wa0 = g_wf[slot == 0 ? 1 : 0], wa1 = g_wf[slot == 0 ? 4 : 3];
    float wb0 = g_wf[slot == 2 ? 1 : 2], wb1 = g_wf[slot == 2 ? 4 : 5];
    float be0 = g_wf[6], be1 = g_wf[7];

    const float4* xr4 = (const float4*)g_xr;
    float4 aself = xr4[c * NT4 + tid];
    // per-thread bases: self-plane contribution + bias (constant over entries)
    float b0x = fmaf(aself.x, ws0, be0), b0y = fmaf(aself.y, ws0, be0);
    float b0z = fmaf(aself.z, ws0, be0), b0w = fmaf(aself.w, ws0, be0);
    float b1x = fmaf(aself.x, ws1, be1), b1y = fmaf(aself.y, ws1, be1);
    float b1z = fmaf(aself.z, ws1, be1), b1w = fmaf(aself.w, ws1, be1);

    __shared__ ushort2 sE[CAP];
    int cnt = min(g_counts[c], CAP);
    for (int i = tid; i < cnt; i += 64) sE[i] = g_entries[c * CAP + i];
    __syncthreads();
    if (tid == 0) g_counts[c] = 0;                  // reset for next replay

    float4 m0 = make_float4(0.f, 0.f, 0.f, 0.f);
    float4 m1 = make_float4(0.f, 0.f, 0.f, 0.f);

    #pragma unroll 4
    for (int i = 0; i < cnt; ++i) {
        ushort2 e = sE[i];
        float4 A = xr4[(int)e.x * NT4 + tid];
        float4 B = xr4[(int)e.y * NT4 + tid];
        m0.x = fmaxf(m0.x, fmaf(A.x, wa0, fmaf(B.x, wb0, b0x)));
        m0.y = fmaxf(m0.y, fmaf(A.y, wa0, fmaf(B.y, wb0, b0y)));
        m0.z = fmaxf(m0.z, fmaf(A.z, wa0, fmaf(B.z, wb0, b0z)));
        m0.w = fmaxf(m0.w, fmaf(A.w, wa0, fmaf(B.w, wb0, b0w)));
        m1.x = fmaxf(m1.x, fmaf(A.x, wa1, fmaf(B.x, wb1, b1x)));
        m1.y = fmaxf(m1.y, fmaf(A.y, wa1, fmaf(B.y, wb1, b1y)));
        m1.z = fmaxf(m1.z, fmaf(A.z, wa1, fmaf(B.z, wb1, b1z)));
        m1.w = fmaxf(m1.w, fmaf(A.w, wa1, fmaf(B.w, wb1, b1w)));
    }

    // out layout (1, 3, NCH, NT): plane 0 written by pre_kernel.
    float4* o4 = (float4*)out;
    o4[NCH * NT4 + c * NT4 + tid]     = m0;
    o4[2 * NCH * NT4 + c * NT4 + tid] = m1;
}

extern "C" void kernel_launch(void* const* d_in, const int* in_sizes, int n_in,
                              void* d_out, int out_size) {
    const float* x  = (const float*)d_in[0];
    const float* W1 = (const float*)d_in[1];
    const float* b1 = (const float*)d_in[2];
    const float* W2 = (const float*)d_in[3];
    const float* b2 = (const float*)d_in[4];
    const int* gi0  = (const int*)d_in[5];
    const int* gi1  = (const int*)d_in[6];
    const int* wc00 = (const int*)d_in[7];
    const int* wc01 = (const int*)d_in[8];
    const int* wc02 = (const int*)d_in[9];
    const int* wc10 = (const int*)d_in[10];
    const int* wc11 = (const int*)d_in[11];
    const int* wc12 = (const int*)d_in[12];

    pre_kernel<<<PREP_BLOCKS + BUILD_BLOCKS + 1, 256>>>(
        x, (float*)d_out, W1, b1, W2, b2,
        gi0, gi1, wc00, wc01, wc02, wc10, wc11, wc12);
    main_kernel<<<NCH, 64>>>((float*)d_out);
}

// round 8
// speedup vs baseline: 1.6288x; 1.0518x over previous
#include <cuda_runtime.h>

// Problem geometry (fixed by reference)
#define NCH    2560      // readout channels
#define NT     256       // ticks
#define NT16   64        // 16B chunks (ulonglong2) per row
#define NCELLS 40000     // cells per face
#define CAP    320       // max entries per output channel (even; Poisson(~100) safe)

// ---- static device scratch (no allocation allowed) ----
__device__ int     g_counts[NCH];           // zero-init at load; main_kernel re-zeroes
__device__ ushort2 g_entries[NCH * CAP];    // per-channel partner pairs, 3.3 MB
__device__ float   g_wf[8];                 // folded: w00,w10,w20,w01,w11,w21,be0,be1

typedef unsigned long long u64;

// Packed f32x2 FMA (sm_100+): d = a*b+c on both 32-bit halves. SASS: FFMA2.
__device__ __forceinline__ u64 fma2(u64 a, u64 b, u64 c) {
    u64 d;
    asm("fma.rn.f32x2 %0, %1, %2, %3;" : "=l"(d) : "l"(a), "l"(b), "l"(c));
    return d;
}
__device__ __forceinline__ float lo32(u64 v) { return __uint_as_float((unsigned)v); }
__device__ __forceinline__ float hi32(u64 v) { return __uint_as_float((unsigned)(v >> 32)); }
__device__ __forceinline__ u64 pack2(float a, float b) {
    return (u64)__float_as_uint(a) | ((u64)__float_as_uint(b) << 32);
}

// Read logical element i from an index table that may be int32 or int64
// (little-endian: lo word first; all values nonnegative < 2^31).
__device__ __forceinline__ int idx_ld(const int* p, int i, bool is64) {
    return is64 ? p[2 * i] : p[i];
}

#define PREP_BLOCKS  640                    // 640*256 threads, one float4 each = NCH*NT/4
#define BUILD_BLOCKS 313                    // ceil(80000/256)

// Fused pre-kernel: relu -> out plane0 (blocks [0,PREP)), bucket build
// (blocks [PREP, PREP+BUILD)), weight fold (last block). g_counts is zero
// (module init on run 1; main_kernel resets it every run).
__global__ void pre_kernel(const float* __restrict__ x, float* __restrict__ out,
                           const float* __restrict__ W1, const float* __restrict__ b1,
                           const float* __restrict__ W2, const float* __restrict__ b2,
                           const int* __restrict__ gi0, const int* __restrict__ gi1,
                           const int* __restrict__ wc00, const int* __restrict__ wc01,
                           const int* __restrict__ wc02, const int* __restrict__ wc10,
                           const int* __restrict__ wc11, const int* __restrict__ wc12) {
    int b = blockIdx.x, tid = threadIdx.x;
    if (b < PREP_BLOCKS) {
        int i = b * 256 + tid;                      // float4 index, < 163840
        float4 v = ((const float4*)x)[i];
        v.x = fmaxf(v.x, 0.f); v.y = fmaxf(v.y, 0.f);
        v.z = fmaxf(v.z, 0.f); v.w = fmaxf(v.w, 0.f);
        ((float4*)out)[i] = v;                      // plane 0 = relu(x); also main's gather src
        return;
    }
    if (b < PREP_BLOCKS + BUILD_BLOCKS) {
        int gid = (b - PREP_BLOCKS) * 256 + tid;
        if (gid >= 2 * NCELLS) return;
        // dtype sniff: int64 => these words are hi-halves (all 0). For int32
        // they are three distinct permutation channels (at most one can be 0).
        bool is64 = (wc00[1] == 0 && wc00[3] == 0 && wc00[5] == 0);
        int f = gid / NCELLS;
        int n = gid - f * NCELLS;
        const int* gi = f ? gi1 : gi0;
        const int* wa = f ? wc10 : wc00;
        const int* wb = f ? wc11 : wc01;
        const int* wd = f ? wc12 : wc02;

        int w0 = idx_ld(gi, n * 3 + 0, is64);
        int w1 = idx_ld(gi, n * 3 + 1, is64);
        int w2 = idx_ld(gi, n * 3 + 2, is64);
        int c0 = idx_ld(wa, w0 * 2 + 1, is64);      // plane 0, in [0,800)
        int c1 = idx_ld(wb, w1 * 2 + 1, is64);      // plane 1, in [800,1600)
        int c2 = idx_ld(wd, w2 * 2 + 1, is64);      // plane 2, in [1600,2560)

        // Bucket c stores the OTHER two channels (slot implied by c's range).
        int s0 = atomicAdd(&g_counts[c0], 1);
        if (s0 < CAP) g_entries[c0 * CAP + s0] =
            make_ushort2((unsigned short)c1, (unsigned short)c2);
        int s1 = atomicAdd(&g_counts[c1], 1);
        if (s1 < CAP) g_entries[c1 * CAP + s1] =
            make_ushort2((unsigned short)c0, (unsigned short)c2);
        int s2 = atomicAdd(&g_counts[c2], 1);
        if (s2 < CAP) g_entries[c2 * CAP + s2] =
            make_ushort2((unsigned short)c0, (unsigned short)c1);
        return;
    }
    // fold block: W1(3x8)@W2(8x2), beff = b1@W2 + b2
    if (tid == 0) {
        float s0 = b2[0], s1 = b2[1];
        float a[6] = {0.f, 0.f, 0.f, 0.f, 0.f, 0.f};
        #pragma unroll
        for (int h = 0; h < 8; ++h) {
            float v0 = W2[h * 2 + 0], v1 = W2[h * 2 + 1];
            s0 = fmaf(b1[h], v0, s0);
            s1 = fmaf(b1[h], v1, s1);
            #pragma unroll
            for (int r = 0; r < 3; ++r) {
                a[r]     = fmaf(W1[r * 8 + h], v0, a[r]);
                a[r + 3] = fmaf(W1[r * 8 + h], v1, a[r + 3]);
            }
        }
        #pragma unroll
        for (int r = 0; r < 6; ++r) g_wf[r] = a[r];
        g_wf[6] = s0; g_wf[7] = s1;
    }
}

// Main: one block per output channel; 64 threads, 4 ticks each (16B).
// Self-row hoisted into per-thread bases; per entry: 2x LDG.128 of partner
// rows + 8 FFMA2 + 8 FMNMX. Gathers from out plane 0 (= relu(x)).
__global__ __launch_bounds__(64) void main_kernel(float* __restrict__ out) {
    int c   = blockIdx.x;
    int tid = threadIdx.x;   // 0..63

    int slot = (c >= 800) + (c >= 1600);            // plane of channel c
    float ws0 = g_wf[slot],              ws1 = g_wf[3 + slot];
    float wa0 = g_wf[slot == 0 ? 1 : 0], wa1 = g_wf[slot == 0 ? 4 : 3];
    float wb0 = g_wf[slot == 2 ? 1 : 2], wb1 = g_wf[slot == 2 ? 4 : 5];
    float be0 = g_wf[6], be1 = g_wf[7];

    const ulonglong2* xr8 = (const ulonglong2*)out;   // plane 0 rows, 16B chunks
    ulonglong2 as = xr8[c * NT16 + tid];
    float sx = lo32(as.x), sy = hi32(as.x), sz = lo32(as.y), sw = hi32(as.y);
    // per-thread bases: self-plane contribution + bias (constant over entries)
    u64 base0lo = pack2(fmaf(sx, ws0, be0), fmaf(sy, ws0, be0));
    u64 base0hi = pack2(fmaf(sz, ws0, be0), fmaf(sw, ws0, be0));
    u64 base1lo = pack2(fmaf(sx, ws1, be1), fmaf(sy, ws1, be1));
    u64 base1hi = pack2(fmaf(sz, ws1, be1), fmaf(sw, ws1, be1));
    u64 wa0p = pack2(wa0, wa0), wb0p = pack2(wb0, wb0);
    u64 wa1p = pack2(wa1, wa1), wb1p = pack2(wb1, wb1);

    __shared__ ushort4 sE4[CAP / 2];
    ushort2* sE = (ushort2*)sE4;
    int cnt = min(g_counts[c], CAP);
    for (int i = tid; i < cnt; i += 64) sE[i] = g_entries[c * CAP + i];
    __syncthreads();
    if (tid == 0) g_counts[c] = 0;                  // reset for next replay

    float m0x = 0.f, m0y = 0.f, m0z = 0.f, m0w = 0.f;
    float m1x = 0.f, m1y = 0.f, m1z = 0.f, m1w = 0.f;

    #define PROC(ea, eb)                                                       \
    {                                                                          \
        ulonglong2 A = xr8[(int)(ea) * NT16 + tid];                            \
        ulonglong2 B = xr8[(int)(eb) * NT16 + tid];                            \
        u64 t;                                                                 \
        t = fma2(A.x, wa0p, base0lo); t = fma2(B.x, wb0p, t);                  \
        m0x = fmaxf(m0x, lo32(t));    m0y = fmaxf(m0y, hi32(t));               \
        t = fma2(A.y, wa0p, base0hi); t = fma2(B.y, wb0p, t);                  \
        m0z = fmaxf(m0z, lo32(t));    m0w = fmaxf(m0w, hi32(t));               \
        t = fma2(A.x, wa1p, base1lo); t = fma2(B.x, wb1p, t);                  \
        m1x = fmaxf(m1x, lo32(t));    m1y = fmaxf(m1y, hi32(t));               \
        t = fma2(A.y, wa1p, base1hi); t = fma2(B.y, wb1p, t);                  \
        m1z = fmaxf(m1z, lo32(t));    m1w = fmaxf(m1w, hi32(t));               \
    }

    int npair = cnt >> 1;
    #pragma unroll 2
    for (int i = 0; i < npair; ++i) {
        ushort4 e2 = sE4[i];
        PROC(e2.x, e2.y);
        PROC(e2.z, e2.w);
    }
    if (cnt & 1) {
        ushort2 e = sE[cnt - 1];
        PROC(e.x, e.y);
    }
    #undef PROC

    // out layout (1, 3, NCH, NT): plane 0 written by pre_kernel.
    float4* o4 = (float4*)out;
    int nt4 = NT / 4;
    o4[NCH * nt4 + c * nt4 + tid]     = make_float4(m0x, m0y, m0z, m0w);
    o4[2 * NCH * nt4 + c * nt4 + tid] = make_float4(m1x, m1y, m1z, m1w);
}

extern "C" void kernel_launch(void* const* d_in, const int* in_sizes, int n_in,
                              void* d_out, int out_size) {
    const float* x  = (const float*)d_in[0];
    const float* W1 = (const float*)d_in[1];
    const float* b1 = (const float*)d_in[2];
    const float* W2 = (const float*)d_in[3];
    const float* b2 = (const float*)d_in[4];
    const int* gi0  = (const int*)d_in[5];
    const int* gi1  = (const int*)d_in[6];
    const int* wc00 = (const int*)d_in[7];
    const int* wc01 = (const int*)d_in[8];
    const int* wc02 = (const int*)d_in[9];
    const int* wc10 = (const int*)d_in[10];
    const int* wc11 = (const int*)d_in[11];
    const int* wc12 = (const int*)d_in[12];

    pre_kernel<<<PREP_BLOCKS + BUILD_BLOCKS + 1, 256>>>(
        x, (float*)d_out, W1, b1, W2, b2,
        gi0, gi1, wc00, wc01, wc02, wc10, wc11, wc12);
    main_kernel<<<NCH, 64>>>((float*)d_out);
}